// round 5
// baseline (speedup 1.0000x reference)
#include <cuda_runtime.h>
#include <cuda_bf16.h>
#include <math.h>
#include <stdint.h>

// ---- problem constants (reference: V,BLK,L,H,D = 50257,1024,8,12,768) ----
#define DD   768
#define TT   1024
#define BB   2
#define MM   2048          // B*T
#define VV   50257
#define LL   8             // !! 8 layers, not 12 !!
#define HH   12
#define HD   64

// ---- device scratch (allocation-free) ----
__device__ int   g_bf16;                 // 1 = inputs (and output) are bf16
__device__ float g_x[MM * DD];
__device__ float g_h[MM * DD];
__device__ float g_qkv[MM * 3 * DD];
__device__ float g_y[MM * DD];
__device__ float g_fc[MM * 4 * DD];
__device__ float g_rowloss[MM];
__device__ float g_logits[(size_t)MM * VV];   // fallback when d_out can't hold logits

// fp32 canonical copies of all float inputs
__device__ float cw_wte[(size_t)VV * DD];
__device__ float cw_wpe[TT * DD];
__device__ float cw_ln1s[LL * DD], cw_ln1b[LL * DD];
__device__ float cw_attnw[(size_t)LL * DD * 3 * DD];
__device__ float cw_attnb[LL * 3 * DD];
__device__ float cw_projw[(size_t)LL * DD * DD];
__device__ float cw_projb[LL * DD];
__device__ float cw_ln2s[LL * DD], cw_ln2b[LL * DD];
__device__ float cw_fcw[(size_t)LL * DD * 4 * DD];
__device__ float cw_fcb[LL * 4 * DD];
__device__ float cw_p2w[(size_t)LL * 4 * DD * DD];
__device__ float cw_p2b[LL * DD];
__device__ float cw_lnfs[DD], cw_lnfb[DD];

// ---- dtype detector: bf16 low-half exponent pattern vs fp32 random mantissa ----
__global__ void detect_kernel(const uint32_t* __restrict__ w) {
    if (threadIdx.x == 0 && blockIdx.x == 0) {
        int hits = 0;
        for (int i = 0; i < 128; i++) {
            uint32_t lo = w[i] & 0xFFFFu;
            uint32_t e = (lo >> 7) & 0xFFu;
            if (e >= 0x66u && e <= 0x8Cu) hits++;
        }
        g_bf16 = (hits >= 64) ? 1 : 0;
    }
}

// ---- generic convert/copy: external buffer -> fp32 scratch ----
__global__ void cvt_kernel(const void* __restrict__ src, float* __restrict__ dst, int n) {
    const int bf = g_bf16;
    for (int i = blockIdx.x * 256 + threadIdx.x; i < n; i += gridDim.x * 256) {
        dst[i] = bf ? __bfloat162float(((const __nv_bfloat16*)src)[i])
                    : ((const float*)src)[i];
    }
}

// ---- reductions ----
__device__ __forceinline__ float warp_sum(float v) {
#pragma unroll
    for (int o = 16; o; o >>= 1) v += __shfl_xor_sync(0xffffffffu, v, o);
    return v;
}
__device__ __forceinline__ float warp_max(float v) {
#pragma unroll
    for (int o = 16; o; o >>= 1) v = fmaxf(v, __shfl_xor_sync(0xffffffffu, v, o));
    return v;
}
__device__ __forceinline__ float block_sum(float v, float* sh) {
    int lane = threadIdx.x & 31, w = threadIdx.x >> 5;
    v = warp_sum(v);
    if (lane == 0) sh[w] = v;
    __syncthreads();
    if (w == 0) {
        float t = (lane < 8) ? sh[lane] : 0.f;
        t = warp_sum(t);
        if (lane == 0) sh[0] = t;
    }
    __syncthreads();
    float r = sh[0];
    __syncthreads();
    return r;
}
__device__ __forceinline__ float block_max(float v, float* sh) {
    int lane = threadIdx.x & 31, w = threadIdx.x >> 5;
    v = warp_max(v);
    if (lane == 0) sh[w] = v;
    __syncthreads();
    if (w == 0) {
        float t = (lane < 8) ? sh[lane] : -1e30f;
        t = warp_max(t);
        if (lane == 0) sh[0] = t;
    }
    __syncthreads();
    float r = sh[0];
    __syncthreads();
    return r;
}

__device__ __forceinline__ float gelu_f(float x) {
    float u = 0.7978845608028654f * (x + 0.044715f * x * x * x);
    float t;
    asm("tanh.approx.f32 %0, %1;" : "=f"(t) : "f"(u));
    return 0.5f * x * (1.f + t);
}

// ---- embedding: x = wte[idx] + wpe[t] ----
__global__ void embed_kernel(const int* __restrict__ idx,
                             const float* __restrict__ wte,
                             const float* __restrict__ wpe,
                             float* __restrict__ x) {
    int i = blockIdx.x;          // 0..2047
    int tok = idx[i];
    if (tok < 0) tok = 0;
    if (tok >= VV) tok = VV - 1;
    int t = i & (TT - 1);
    const float* wr = wte + (size_t)tok * DD;
    const float* pr = wpe + (size_t)t * DD;
    float* xr = x + (size_t)i * DD;
    for (int c = threadIdx.x; c < DD; c += 256)
        xr[c] = wr[c] + pr[c];
}

// ---- layernorm, one block per row ----
__global__ void ln_kernel(const float* __restrict__ x,
                          const float* __restrict__ g,
                          const float* __restrict__ b,
                          float* __restrict__ o) {
    __shared__ float sh[8];
    int row = blockIdx.x, tid = threadIdx.x;
    const float* xr = x + (size_t)row * DD;
    float v0 = xr[tid], v1 = xr[tid + 256], v2 = xr[tid + 512];
    float mu = block_sum(v0 + v1 + v2, sh) * (1.f / 768.f);
    float d0 = v0 - mu, d1 = v1 - mu, d2 = v2 - mu;
    float var = block_sum(d0 * d0 + d1 * d1 + d2 * d2, sh) * (1.f / 768.f);
    float rstd = rsqrtf(var + 1e-5f);
    float* orow = o + (size_t)row * DD;
    orow[tid]       = d0 * rstd * g[tid]       + b[tid];
    orow[tid + 256] = d1 * rstd * g[tid + 256] + b[tid + 256];
    orow[tid + 512] = d2 * rstd * g[tid + 512] + b[tid + 512];
}

// ---- GEMM: C[M,N] = A[M,K] @ B + epilogue (all operands fp32) ----
// TB=false: B is [K,N] row-major (N multiple of 128). TB=true: C = A @ B^T.
// EPI: 0 = +bias ; 1 = gelu(+bias) ; 2 = +bias+res ; 3 = none
// DYNOUT: store dtype chosen by g_bf16 at runtime.
template <bool TB, int EPI, bool DYNOUT>
__global__ __launch_bounds__(256, 2)
void gemm_kernel(const float* __restrict__ A, const float* __restrict__ B,
                 const float* __restrict__ bias, const float* __restrict__ res,
                 void* __restrict__ Cv, int N, int K) {
    __shared__ __align__(16) float As[8][128];
    __shared__ __align__(16) float Bs[8][128];
    const int bm = blockIdx.y << 7;
    const int bn = blockIdx.x << 7;
    const int tid = threadIdx.x;
    const int tx = tid & 15;
    const int ty = tid >> 4;
    const int lrow = tid >> 1;          // 0..127
    const int lk4 = (tid & 1) << 2;     // 0 or 4
    const int out_bf = DYNOUT ? g_bf16 : 0;

    float acc[8][8];
#pragma unroll
    for (int i = 0; i < 8; i++)
#pragma unroll
        for (int j = 0; j < 8; j++) acc[i][j] = 0.f;

    const float* Ap = A + (size_t)(bm + lrow) * K + lk4;
    const float* BpT = B + (size_t)(bn + lrow) * K + lk4;          // TB path
    const float* BpN = B + (size_t)(tid >> 5) * N + bn + ((tid & 31) << 2); // !TB
    const bool tb_ok = TB ? ((bn + lrow) < N) : true;

    for (int k0 = 0; k0 < K; k0 += 8) {
        float4 av = *(const float4*)(Ap + k0);
        As[lk4 + 0][lrow] = av.x;
        As[lk4 + 1][lrow] = av.y;
        As[lk4 + 2][lrow] = av.z;
        As[lk4 + 3][lrow] = av.w;
        if (TB) {
            float4 bv = make_float4(0.f, 0.f, 0.f, 0.f);
            if (tb_ok) bv = *(const float4*)(BpT + k0);
            Bs[lk4 + 0][lrow] = bv.x;
            Bs[lk4 + 1][lrow] = bv.y;
            Bs[lk4 + 2][lrow] = bv.z;
            Bs[lk4 + 3][lrow] = bv.w;
        } else {
            *(float4*)&Bs[tid >> 5][(tid & 31) << 2] =
                *(const float4*)(BpN + (size_t)k0 * N);
        }
        __syncthreads();
#pragma unroll
        for (int kk = 0; kk < 8; kk++) {
            float a[8], b[8];
            *(float4*)(a)     = *(const float4*)&As[kk][ty << 2];
            *(float4*)(a + 4) = *(const float4*)&As[kk][64 + (ty << 2)];
            *(float4*)(b)     = *(const float4*)&Bs[kk][tx << 2];
            *(float4*)(b + 4) = *(const float4*)&Bs[kk][64 + (tx << 2)];
#pragma unroll
            for (int i = 0; i < 8; i++)
#pragma unroll
                for (int j = 0; j < 8; j++)
                    acc[i][j] = fmaf(a[i], b[j], acc[i][j]);
        }
        __syncthreads();
    }

#pragma unroll
    for (int i = 0; i < 8; i++) {
        int m = bm + ((i < 4) ? ((ty << 2) + i) : (64 + (ty << 2) + i - 4));
        const size_t rowoff = (size_t)m * N;
        const float* rrow = (EPI == 2) ? (res + rowoff) : nullptr;
#pragma unroll
        for (int j = 0; j < 8; j++) {
            int n = bn + ((j < 4) ? ((tx << 2) + j) : (64 + (tx << 2) + j - 4));
            if (TB && n >= N) continue;
            float v = acc[i][j];
            if (EPI != 3) v += bias[n];
            if (EPI == 1) v = gelu_f(v);
            if (EPI == 2) v += rrow[n];
            if (DYNOUT && out_bf)
                ((__nv_bfloat16*)Cv)[rowoff + n] = __float2bfloat16(v);
            else
                ((float*)Cv)[rowoff + n] = v;
        }
    }
}

// ---- causal attention: one warp per (b,h,t) query row, online softmax ----
__global__ void attn_kernel(const float* __restrict__ qkv, float* __restrict__ y) {
    const int t = blockIdx.x, h = blockIdx.y, b = blockIdx.z;
    const int lane = threadIdx.x;
    const float scale = 0.125f;  // 1/sqrt(64)
    const size_t rowq = (size_t)(b * TT + t) * (3 * DD) + h * HD;
    float q0 = qkv[rowq + lane] * scale;
    float q1 = qkv[rowq + 32 + lane] * scale;
    const float* kbase = qkv + (size_t)b * TT * 3 * DD + DD + h * HD;
    const float* vbase = kbase + DD;
    float m = -1e30f, l = 0.f, a0 = 0.f, a1 = 0.f;
    for (int j = 0; j <= t; j++) {
        const float* kp = kbase + (size_t)j * (3 * DD);
        float s = q0 * kp[lane] + q1 * kp[32 + lane];
        s = warp_sum(s);
        float mn = fmaxf(m, s);
        float corr = __expf(m - mn);
        float p = __expf(s - mn);
        const float* vp = vbase + (size_t)j * (3 * DD);
        a0 = a0 * corr + p * vp[lane];
        a1 = a1 * corr + p * vp[32 + lane];
        l = l * corr + p;
        m = mn;
    }
    float inv = 1.f / l;
    size_t oy = (size_t)(b * TT + t) * DD + h * HD;
    y[oy + lane] = a0 * inv;
    y[oy + 32 + lane] = a1 * inv;
}

// ---- loss: per-row logsumexp + target gather ----
// LOG_BF: logits buffer is bf16 (only true when writing bf16 into d_out)
template <bool DYN>
__global__ void loss_rows_kernel(const void* __restrict__ logits,
                                 const int* __restrict__ targets,
                                 float* __restrict__ rowloss) {
    __shared__ float sh[8];
    const int bf = DYN ? g_bf16 : 0;
    int row = blockIdx.x, tid = threadIdx.x;
    const size_t base = (size_t)row * VV;
    float mx = -1e30f;
    for (int c = tid; c < VV; c += 256) {
        float v = bf ? __bfloat162float(((const __nv_bfloat16*)logits)[base + c])
                     : ((const float*)logits)[base + c];
        mx = fmaxf(mx, v);
    }
    mx = block_max(mx, sh);
    float s = 0.f;
    for (int c = tid; c < VV; c += 256) {
        float v = bf ? __bfloat162float(((const __nv_bfloat16*)logits)[base + c])
                     : ((const float*)logits)[base + c];
        s += __expf(v - mx);
    }
    s = block_sum(s, sh);
    if (tid == 0) {
        int tg = targets[row];
        if (tg < 0) tg = 0;
        if (tg >= VV) tg = VV - 1;
        float lt = bf ? __bfloat162float(((const __nv_bfloat16*)logits)[base + tg])
                      : ((const float*)logits)[base + tg];
        rowloss[row] = -(lt - mx - logf(s));
    }
}
__global__ void loss_final_kernel(const float* __restrict__ rowloss,
                                  void* __restrict__ out, long long elem_off) {
    __shared__ float sh[8];
    const int bf = g_bf16;
    float s = 0.f;
    for (int i = threadIdx.x; i < MM; i += 256) s += rowloss[i];
    s = block_sum(s, sh);
    if (threadIdx.x == 0) {
        float v = s * (1.f / (float)MM);
        if (bf) ((__nv_bfloat16*)out)[elem_off] = __float2bfloat16(v);
        else    ((float*)out)[elem_off] = v;
    }
}

static inline void cvt(const void* src, float* dst, long long n) {
    int grid = (int)((n + 255) / 256);
    if (grid > 4096) grid = 4096;
    cvt_kernel<<<grid, 256>>>(src, dst, (int)n);
}

extern "C" void kernel_launch(void* const* d_in, const int* in_sizes, int n_in,
                              void* d_out, int out_size) {
    // Input-order detection by size fingerprint: insertion order starts with
    // idx (2048 elements); alphabetical starts with attn_b (8*2304 = 18432).
    const int *idx, *targets;
    const void *wte, *wpe, *ln1_s, *ln1_b, *attn_w, *attn_b, *proj_w, *proj_b;
    const void *ln2_s, *ln2_b, *fc_w, *fc_b, *proj2_w, *proj2_b, *lnf_s, *lnf_b;

    if (n_in >= 18 && in_sizes[0] != 2048) {
        // alphabetical: attn_b, attn_w, fc_b, fc_w, idx, ln1_b, ln1_s, ln2_b,
        //               ln2_s, lnf_b, lnf_s, proj2_b, proj2_w, proj_b, proj_w,
        //               targets, wpe, wte
        attn_b  = d_in[0];  attn_w  = d_in[1];  fc_b    = d_in[2];  fc_w    = d_in[3];
        idx     = (const int*)d_in[4];
        ln1_b   = d_in[5];  ln1_s   = d_in[6];  ln2_b   = d_in[7];  ln2_s   = d_in[8];
        lnf_b   = d_in[9];  lnf_s   = d_in[10];
        proj2_b = d_in[11]; proj2_w = d_in[12]; proj_b  = d_in[13]; proj_w  = d_in[14];
        targets = (const int*)d_in[15];
        wpe     = d_in[16]; wte     = d_in[17];
    } else {
        // setup_inputs insertion order
        idx     = (const int*)d_in[0];
        targets = (const int*)d_in[1];
        wte     = d_in[2];  wpe     = d_in[3];
        ln1_s   = d_in[4];  ln1_b   = d_in[5];
        attn_w  = d_in[6];  attn_b  = d_in[7];
        proj_w  = d_in[8];  proj_b  = d_in[9];
        ln2_s   = d_in[10]; ln2_b   = d_in[11];
        fc_w    = d_in[12]; fc_b    = d_in[13];
        proj2_w = d_in[14]; proj2_b = d_in[15];
        lnf_s   = d_in[16]; lnf_b   = d_in[17];
    }

    float *x, *h, *qkv, *y, *fc, *rowloss, *logits_scratch;
    cudaGetSymbolAddress((void**)&x, g_x);
    cudaGetSymbolAddress((void**)&h, g_h);
    cudaGetSymbolAddress((void**)&qkv, g_qkv);
    cudaGetSymbolAddress((void**)&y, g_y);
    cudaGetSymbolAddress((void**)&fc, g_fc);
    cudaGetSymbolAddress((void**)&rowloss, g_rowloss);
    cudaGetSymbolAddress((void**)&logits_scratch, g_logits);

    float *wtef, *wpef, *ln1sf, *ln1bf, *attnwf, *attnbf, *projwf, *projbf;
    float *ln2sf, *ln2bf, *fcwf, *fcbf, *p2wf, *p2bf, *lnfsf, *lnfbf;
    cudaGetSymbolAddress((void**)&wtef, cw_wte);
    cudaGetSymbolAddress((void**)&wpef, cw_wpe);
    cudaGetSymbolAddress((void**)&ln1sf, cw_ln1s);
    cudaGetSymbolAddress((void**)&ln1bf, cw_ln1b);
    cudaGetSymbolAddress((void**)&attnwf, cw_attnw);
    cudaGetSymbolAddress((void**)&attnbf, cw_attnb);
    cudaGetSymbolAddress((void**)&projwf, cw_projw);
    cudaGetSymbolAddress((void**)&projbf, cw_projb);
    cudaGetSymbolAddress((void**)&ln2sf, cw_ln2s);
    cudaGetSymbolAddress((void**)&ln2bf, cw_ln2b);
    cudaGetSymbolAddress((void**)&fcwf, cw_fcw);
    cudaGetSymbolAddress((void**)&fcbf, cw_fcb);
    cudaGetSymbolAddress((void**)&p2wf, cw_p2w);
    cudaGetSymbolAddress((void**)&p2bf, cw_p2b);
    cudaGetSymbolAddress((void**)&lnfsf, cw_lnfs);
    cudaGetSymbolAddress((void**)&lnfbf, cw_lnfb);

    // 1) detect dtype from wte bit patterns
    detect_kernel<<<1, 32>>>((const uint32_t*)wte);

    // 2) convert all float inputs to fp32 scratch (L = 8!)
    cvt(wte,     wtef,  (long long)VV * DD);
    cvt(wpe,     wpef,  TT * DD);
    cvt(ln1_s,   ln1sf, LL * DD);
    cvt(ln1_b,   ln1bf, LL * DD);
    cvt(attn_w,  attnwf,(long long)LL * DD * 3 * DD);
    cvt(attn_b,  attnbf, LL * 3 * DD);
    cvt(proj_w,  projwf,(long long)LL * DD * DD);
    cvt(proj_b,  projbf, LL * DD);
    cvt(ln2_s,   ln2sf, LL * DD);
    cvt(ln2_b,   ln2bf, LL * DD);
    cvt(fc_w,    fcwf,  (long long)LL * DD * 4 * DD);
    cvt(fc_b,    fcbf,  LL * 4 * DD);
    cvt(proj2_w, p2wf,  (long long)LL * 4 * DD * DD);
    cvt(proj2_b, p2bf,  LL * DD);
    cvt(lnf_s,   lnfsf, DD);
    cvt(lnf_b,   lnfbf, DD);

    const long long NL = (long long)MM * VV;   // 102,926,336
    const bool logits_fit = ((long long)out_size >= NL);

    embed_kernel<<<MM, 256>>>(idx, wtef, wpef, x);

    for (int l = 0; l < LL; l++) {
        // --- attention block ---
        ln_kernel<<<MM, 256>>>(x, ln1sf + l * DD, ln1bf + l * DD, h);
        gemm_kernel<false, 0, false><<<dim3(3 * DD / 128, MM / 128), 256>>>(
            h, attnwf + (size_t)l * DD * 3 * DD, attnbf + l * 3 * DD, nullptr,
            qkv, 3 * DD, DD);
        attn_kernel<<<dim3(TT, HH, BB), 32>>>(qkv, y);
        gemm_kernel<false, 2, false><<<dim3(DD / 128, MM / 128), 256>>>(
            y, projwf + (size_t)l * DD * DD, projbf + l * DD, x, x, DD, DD);
        // --- MLP block ---
        ln_kernel<<<MM, 256>>>(x, ln2sf + l * DD, ln2bf + l * DD, h);
        gemm_kernel<false, 1, false><<<dim3(4 * DD / 128, MM / 128), 256>>>(
            h, fcwf + (size_t)l * DD * 4 * DD, fcbf + l * 4 * DD, nullptr,
            fc, 4 * DD, DD);
        gemm_kernel<false, 2, false><<<dim3(DD / 128, MM / 128), 256>>>(
            fc, p2wf + (size_t)l * 4 * DD * DD, p2bf + l * DD, x, x,
            DD, 4 * DD);
    }

    // --- final LN + tied lm_head ---
    ln_kernel<<<MM, 256>>>(x, lnfsf, lnfbf, h);
    if (logits_fit) {
        gemm_kernel<true, 3, true><<<dim3((VV + 127) / 128, MM / 128), 256>>>(
            h, wtef, nullptr, nullptr, d_out, VV, DD);
        if ((long long)out_size > NL) {
            loss_rows_kernel<true><<<MM, 256>>>(d_out, targets, rowloss);
            loss_final_kernel<<<1, 256>>>(rowloss, d_out, NL);
        }
    } else {
        gemm_kernel<true, 3, false><<<dim3((VV + 127) / 128, MM / 128), 256>>>(
            h, wtef, nullptr, nullptr, logits_scratch, VV, DD);
        if (out_size >= 1) {
            loss_rows_kernel<false><<<MM, 256>>>(logits_scratch, targets, rowloss);
            loss_final_kernel<<<1, 256>>>(rowloss, d_out, 0);
        }
    }
}

// round 7
// speedup vs baseline: 1.2121x; 1.2121x over previous
#include <cuda_runtime.h>
#include <cuda_bf16.h>
#include <math.h>
#include <stdint.h>

// ---- problem constants (V,BLK,L,H,D = 50257,1024,8,12,768) ----
#define DD   768
#define TT   1024
#define BB   2
#define MM   2048
#define VV   50257
#define LL   8
#define HH   12
#define HD   64

// ---- device scratch (allocation-free) ----
__device__ int   g_bf16;
__device__ float g_x[MM * DD];
__device__ float g_qkv[MM * 3 * DD];
__device__ float g_rowloss[MM];
__device__ float g_logits[(size_t)MM * VV];

__device__ __nv_bfloat16 g_h_hi[MM * DD],  g_h_lo[MM * DD];
__device__ __nv_bfloat16 g_y_hi[MM * DD],  g_y_lo[MM * DD];
__device__ __nv_bfloat16 g_fc_hi[MM * 4 * DD], g_fc_lo[MM * 4 * DD];

// fp32 canonical small params + wte/wpe for embedding
__device__ float cw_wte[(size_t)VV * DD];
__device__ float cw_wpe[TT * DD];
__device__ float cw_ln1s[LL * DD], cw_ln1b[LL * DD];
__device__ float cw_attnb[LL * 3 * DD];
__device__ float cw_projb[LL * DD];
__device__ float cw_ln2s[LL * DD], cw_ln2b[LL * DD];
__device__ float cw_fcb[LL * 4 * DD];
__device__ float cw_p2b[LL * DD];
__device__ float cw_lnfs[DD], cw_lnfb[DD];

// split-bf16 weights, [N,K] K-major
__device__ __nv_bfloat16 tw_attn_hi[(size_t)LL * 3 * DD * DD], tw_attn_lo[(size_t)LL * 3 * DD * DD];
__device__ __nv_bfloat16 tw_proj_hi[(size_t)LL * DD * DD],     tw_proj_lo[(size_t)LL * DD * DD];
__device__ __nv_bfloat16 tw_fc_hi[(size_t)LL * 4 * DD * DD],   tw_fc_lo[(size_t)LL * 4 * DD * DD];
__device__ __nv_bfloat16 tw_p2_hi[(size_t)LL * 4 * DD * DD],   tw_p2_lo[(size_t)LL * 4 * DD * DD];
__device__ __nv_bfloat16 wte_hi[(size_t)VV * DD],              wte_lo[(size_t)VV * DD];

// ---- small helpers ----
__device__ __forceinline__ uint32_t smem_u32(const void* p) {
    uint32_t a;
    asm("{ .reg .u64 t; cvta.to.shared.u64 t, %1; cvt.u32.u64 %0, t; }" : "=r"(a) : "l"(p));
    return a;
}
__device__ __forceinline__ void ldm_x4(uint32_t& r0, uint32_t& r1, uint32_t& r2, uint32_t& r3,
                                       uint32_t addr) {
    asm volatile("ldmatrix.sync.aligned.m8n8.x4.shared.b16 {%0,%1,%2,%3}, [%4];"
                 : "=r"(r0), "=r"(r1), "=r"(r2), "=r"(r3) : "r"(addr));
}
__device__ __forceinline__ void mma_bf16(float* c, uint32_t a0, uint32_t a1, uint32_t a2,
                                         uint32_t a3, uint32_t b0, uint32_t b1) {
    asm volatile("mma.sync.aligned.m16n8k16.row.col.f32.bf16.bf16.f32 "
                 "{%0,%1,%2,%3},{%4,%5,%6,%7},{%8,%9},{%0,%1,%2,%3};"
                 : "+f"(c[0]), "+f"(c[1]), "+f"(c[2]), "+f"(c[3])
                 : "r"(a0), "r"(a1), "r"(a2), "r"(a3), "r"(b0), "r"(b1));
}
__device__ __forceinline__ uint32_t packb(float x, float y) {
    uint32_t lo = __bfloat16_as_ushort(__float2bfloat16(x));
    uint32_t hi = __bfloat16_as_ushort(__float2bfloat16(y));
    return lo | (hi << 16);
}
__device__ __forceinline__ void split2(float v, __nv_bfloat16& h, __nv_bfloat16& l) {
    h = __float2bfloat16(v);
    l = __float2bfloat16(v - __bfloat162float(h));
}

// ---- dtype detector ----
__global__ void detect_kernel(const uint32_t* __restrict__ w) {
    if (threadIdx.x == 0 && blockIdx.x == 0) {
        int hits = 0;
        for (int i = 0; i < 128; i++) {
            uint32_t e = ((w[i] & 0xFFFFu) >> 7) & 0xFFu;
            if (e >= 0x66u && e <= 0x8Cu) hits++;
        }
        g_bf16 = (hits >= 64) ? 1 : 0;
    }
}
__device__ __forceinline__ float load_dyn(const void* src, size_t i, int bf) {
    return bf ? __bfloat162float(((const __nv_bfloat16*)src)[i]) : ((const float*)src)[i];
}
__global__ void cvt_kernel(const void* __restrict__ src, float* __restrict__ dst, int n) {
    const int bf = g_bf16;
    for (int i = blockIdx.x * 256 + threadIdx.x; i < n; i += gridDim.x * 256)
        dst[i] = load_dyn(src, i, bf);
}
__global__ void wsplit_kernel(const void* __restrict__ src,
                              __nv_bfloat16* __restrict__ hi, __nv_bfloat16* __restrict__ lo,
                              long long n) {
    const int bf = g_bf16;
    for (long long i = blockIdx.x * 256LL + threadIdx.x; i < n; i += (long long)gridDim.x * 256) {
        float v = load_dyn(src, (size_t)i, bf);
        __nv_bfloat16 h, l;
        split2(v, h, l);
        hi[i] = h;
        lo[i] = l;
    }
}
// transpose+split: W[K,N] (layer z) -> hi/lo [N,K]
__global__ void tsplit_kernel(const void* __restrict__ src,
                              __nv_bfloat16* __restrict__ hi, __nv_bfloat16* __restrict__ lo,
                              int K, int N) {
    __shared__ float tile[32][33];
    const int bf = g_bf16;
    const size_t mat = (size_t)K * N * blockIdx.z;
    const int n0 = blockIdx.x * 32, k0 = blockIdx.y * 32;
    for (int i = threadIdx.y; i < 32; i += 8) {
        int k = k0 + i, n = n0 + threadIdx.x;
        tile[i][threadIdx.x] = load_dyn(src, mat + (size_t)k * N + n, bf);
    }
    __syncthreads();
    for (int i = threadIdx.y; i < 32; i += 8) {
        int n = n0 + i, k = k0 + threadIdx.x;
        float v = tile[threadIdx.x][i];
        __nv_bfloat16 h, l;
        split2(v, h, l);
        size_t o = mat + (size_t)n * K + k;
        hi[o] = h;
        lo[o] = l;
    }
}

// ---- reductions ----
__device__ __forceinline__ float warp_sum(float v) {
#pragma unroll
    for (int o = 16; o; o >>= 1) v += __shfl_xor_sync(0xffffffffu, v, o);
    return v;
}
__device__ __forceinline__ float warp_max(float v) {
#pragma unroll
    for (int o = 16; o; o >>= 1) v = fmaxf(v, __shfl_xor_sync(0xffffffffu, v, o));
    return v;
}
__device__ __forceinline__ float block_sum(float v, float* sh) {
    int lane = threadIdx.x & 31, w = threadIdx.x >> 5;
    v = warp_sum(v);
    if (lane == 0) sh[w] = v;
    __syncthreads();
    if (w == 0) {
        float t = (lane < 8) ? sh[lane] : 0.f;
        t = warp_sum(t);
        if (lane == 0) sh[0] = t;
    }
    __syncthreads();
    float r = sh[0];
    __syncthreads();
    return r;
}
__device__ __forceinline__ float block_max(float v, float* sh) {
    int lane = threadIdx.x & 31, w = threadIdx.x >> 5;
    v = warp_max(v);
    if (lane == 0) sh[w] = v;
    __syncthreads();
    if (w == 0) {
        float t = (lane < 8) ? sh[lane] : -1e30f;
        t = warp_max(t);
        if (lane == 0) sh[0] = t;
    }
    __syncthreads();
    float r = sh[0];
    __syncthreads();
    return r;
}
__device__ __forceinline__ float gelu_f(float x) {
    float u = 0.7978845608028654f * (x + 0.044715f * x * x * x);
    float t;
    asm("tanh.approx.f32 %0, %1;" : "=f"(t) : "f"(u));
    return 0.5f * x * (1.f + t);
}

// ---- embedding ----
__global__ void embed_kernel(const int* __restrict__ idx, const float* __restrict__ wte,
                             const float* __restrict__ wpe, float* __restrict__ x) {
    int i = blockIdx.x;
    int tok = idx[i];
    if (tok < 0) tok = 0;
    if (tok >= VV) tok = VV - 1;
    int t = i & (TT - 1);
    const float* wr = wte + (size_t)tok * DD;
    const float* pr = wpe + (size_t)t * DD;
    float* xr = x + (size_t)i * DD;
    for (int c = threadIdx.x; c < DD; c += 256)
        xr[c] = wr[c] + pr[c];
}

// ---- layernorm -> split bf16 ----
__global__ void ln_kernel(const float* __restrict__ x, const float* __restrict__ g,
                          const float* __restrict__ b,
                          __nv_bfloat16* __restrict__ ohi, __nv_bfloat16* __restrict__ olo) {
    __shared__ float sh[8];
    int row = blockIdx.x, tid = threadIdx.x;
    const float* xr = x + (size_t)row * DD;
    float v0 = xr[tid], v1 = xr[tid + 256], v2 = xr[tid + 512];
    float mu = block_sum(v0 + v1 + v2, sh) * (1.f / 768.f);
    float d0 = v0 - mu, d1 = v1 - mu, d2 = v2 - mu;
    float var = block_sum(d0 * d0 + d1 * d1 + d2 * d2, sh) * (1.f / 768.f);
    float rstd = rsqrtf(var + 1e-5f);
    size_t ro = (size_t)row * DD;
    float o0 = d0 * rstd * g[tid] + b[tid];
    float o1 = d1 * rstd * g[tid + 256] + b[tid + 256];
    float o2 = d2 * rstd * g[tid + 512] + b[tid + 512];
    __nv_bfloat16 h, l;
    split2(o0, h, l); ohi[ro + tid] = h;        olo[ro + tid] = l;
    split2(o1, h, l); ohi[ro + tid + 256] = h;  olo[ro + tid + 256] = l;
    split2(o2, h, l); ohi[ro + tid + 512] = h;  olo[ro + tid + 512] = l;
}

// =======================================================================
// HMMA split-bf16 GEMM: C[M,N] = A @ B^T,  A hi/lo [M,K], B hi/lo [N,K].
// Block 256 thr (8 warps, 2x4), tile BM x 128, BK=32. Warp tile (BM/2)x32.
// MFW: m16-frags per warp (4 -> BM=128, 2 -> BM=64).
// EPI: 0 +bias | 1 gelu(+bias) | 2 +bias+res | 3 none
// OUT: 0 f32 C0 | 1 split bf16 (C0 hi, C1 lo) | 2 dyn d_out (g_bf16)
// NGUARD implies EPI==3.
// =======================================================================
#define PITCH 40

template <int MFW, int EPI, int OUT, bool NGUARD>
__global__ void __launch_bounds__(256)
hgemm_kernel(const __nv_bfloat16* __restrict__ Ahi, const __nv_bfloat16* __restrict__ Alo,
             const __nv_bfloat16* __restrict__ Bhi, const __nv_bfloat16* __restrict__ Blo,
             const float* __restrict__ bias, const float* __restrict__ res,
             void* __restrict__ C0, void* __restrict__ C1, int N, int K) {
    constexpr int BM = MFW * 32;
    __shared__ __align__(16) __nv_bfloat16 sAhi[BM * PITCH], sAlo[BM * PITCH];
    __shared__ __align__(16) __nv_bfloat16 sBhi[128 * PITCH], sBlo[128 * PITCH];
    const int tid = threadIdx.x, lane = tid & 31, wid = tid >> 5;
    const int wm = wid >> 2, wn = wid & 3;
    const int bm = blockIdx.y * BM, bn = blockIdx.x * 128;
    const int out_bf = (OUT == 2) ? g_bf16 : 0;

    float acc[MFW][4][4];
#pragma unroll
    for (int i = 0; i < MFW; i++)
#pragma unroll
        for (int j = 0; j < 4; j++)
#pragma unroll
            for (int q = 0; q < 4; q++) acc[i][j][q] = 0.f;

    const uint32_t uAhi = smem_u32(sAhi), uAlo = smem_u32(sAlo);
    const uint32_t uBhi = smem_u32(sBhi), uBlo = smem_u32(sBlo);

    for (int kc = 0; kc < K; kc += 32) {
        // A tiles: BM rows x 32 bf16 (hi & lo), uint4 copies
        constexpr int AIT = (BM * 4) / 256;
#pragma unroll
        for (int it = 0; it < AIT; it++) {
            int idx = tid + it * 256;
            int row = idx >> 2, seg = idx & 3;
            size_t base = (size_t)(bm + row) * K + kc + seg * 8;
            *(uint4*)(&sAhi[row * PITCH + seg * 8]) = *(const uint4*)(Ahi + base);
            *(uint4*)(&sAlo[row * PITCH + seg * 8]) = *(const uint4*)(Alo + base);
        }
        // B tiles: 128 rows x 32 bf16
#pragma unroll
        for (int it = 0; it < 2; it++) {
            int idx = tid + it * 256;
            int row = idx >> 2, seg = idx & 3;
            uint4 hv = make_uint4(0, 0, 0, 0), lv = make_uint4(0, 0, 0, 0);
            if (!NGUARD || (bn + row) < N) {
                size_t base = (size_t)(bn + row) * K + kc + seg * 8;
                hv = *(const uint4*)(Bhi + base);
                lv = *(const uint4*)(Blo + base);
            }
            *(uint4*)(&sBhi[row * PITCH + seg * 8]) = hv;
            *(uint4*)(&sBlo[row * PITCH + seg * 8]) = lv;
        }
        __syncthreads();
#pragma unroll
        for (int ks = 0; ks < 2; ks++) {
            const int col = ks * 16 + ((lane >> 4) << 3);
            uint32_t bh[4][2], bl[4][2];
#pragma unroll
            for (int g = 0; g < 2; g++) {
                int nrow = wn * 32 + g * 16 + (lane & 15);
                uint32_t r0, r1, r2, r3;
                ldm_x4(r0, r1, r2, r3, uBhi + (nrow * PITCH + col) * 2);
                bh[g * 2 + 0][0] = r0; bh[g * 2 + 0][1] = r2;
                bh[g * 2 + 1][0] = r1; bh[g * 2 + 1][1] = r3;
                ldm_x4(r0, r1, r2, r3, uBlo + (nrow * PITCH + col) * 2);
                bl[g * 2 + 0][0] = r0; bl[g * 2 + 0][1] = r2;
                bl[g * 2 + 1][0] = r1; bl[g * 2 + 1][1] = r3;
            }
#pragma unroll
            for (int mf = 0; mf < MFW; mf++) {
                int arow = wm * (16 * MFW) + mf * 16 + (lane & 15);
                uint32_t a0, a1, a2, a3;
                ldm_x4(a0, a1, a2, a3, uAhi + (arow * PITCH + col) * 2);
#pragma unroll
                for (int nf = 0; nf < 4; nf++) {
                    mma_bf16(acc[mf][nf], a0, a1, a2, a3, bh[nf][0], bh[nf][1]);
                    mma_bf16(acc[mf][nf], a0, a1, a2, a3, bl[nf][0], bl[nf][1]);
                }
                ldm_x4(a0, a1, a2, a3, uAlo + (arow * PITCH + col) * 2);
#pragma unroll
                for (int nf = 0; nf < 4; nf++)
                    mma_bf16(acc[mf][nf], a0, a1, a2, a3, bh[nf][0], bh[nf][1]);
            }
        }
        __syncthreads();
    }

    // ---- epilogue ----
#pragma unroll
    for (int mf = 0; mf < MFW; mf++) {
#pragma unroll
        for (int half = 0; half < 2; half++) {
            int row = bm + wm * (16 * MFW) + mf * 16 + (lane >> 2) + half * 8;
            size_t ro = (size_t)row * N;
#pragma unroll
            for (int nf = 0; nf < 4; nf++) {
                int col = bn + wn * 32 + nf * 8 + (lane & 3) * 2;
                float v0 = acc[mf][nf][half * 2 + 0];
                float v1 = acc[mf][nf][half * 2 + 1];
                if (EPI != 3) { v0 += bias[col]; v1 += bias[col + 1]; }
                if (EPI == 1) { v0 = gelu_f(v0); v1 = gelu_f(v1); }
                if (EPI == 2) { v0 += res[ro + col]; v1 += res[ro + col + 1]; }
                if (OUT == 0) {
                    if (!NGUARD) {
                        *(float2*)((float*)C0 + ro + col) = make_float2(v0, v1);
                    } else {
                        if (col < N)     ((float*)C0)[ro + col] = v0;
                        if (col + 1 < N) ((float*)C0)[ro + col + 1] = v1;
                    }
                } else if (OUT == 1) {
                    __nv_bfloat16 h0, l0, h1, l1;
                    split2(v0, h0, l0);
                    split2(v1, h1, l1);
                    uint32_t hp = (uint32_t)__bfloat16_as_ushort(h0) |
                                  ((uint32_t)__bfloat16_as_ushort(h1) << 16);
                    uint32_t lp = (uint32_t)__bfloat16_as_ushort(l0) |
                                  ((uint32_t)__bfloat16_as_ushort(l1) << 16);
                    *(uint32_t*)((__nv_bfloat16*)C0 + ro + col) = hp;
                    *(uint32_t*)((__nv_bfloat16*)C1 + ro + col) = lp;
                } else {
                    if (out_bf) {
                        if (!NGUARD || col + 1 < N) {
                            if (!NGUARD || col < N)
                                *(uint32_t*)((__nv_bfloat16*)C0 + ro + col) = packb(v0, v1);
                        } else if (col < N) {
                            ((__nv_bfloat16*)C0)[ro + col] = __float2bfloat16(v0);
                        }
                    } else {
                        if (!NGUARD) {
                            *(float2*)((float*)C0 + ro + col) = make_float2(v0, v1);
                        } else {
                            if (col < N)     ((float*)C0)[ro + col] = v0;
                            if (col + 1 < N) ((float*)C0)[ro + col + 1] = v1;
                        }
                    }
                }
            }
        }
    }
}

// ---- causal attention: lane-per-key flash, warp per query, 8 warps/block ----
__global__ void attn_kernel(const float* __restrict__ qkv,
                            __nv_bfloat16* __restrict__ yhi, __nv_bfloat16* __restrict__ ylo) {
    const int lane = threadIdx.x & 31, wid = threadIdx.x >> 5;
    const int t = blockIdx.x * 8 + wid;
    const int h = blockIdx.y, b = blockIdx.z;
    const float scale = 0.125f;
    const size_t rowq = (size_t)(b * TT + t) * (3 * DD) + h * HD;
    float q0 = qkv[rowq + lane] * scale;
    float q1 = qkv[rowq + 32 + lane] * scale;
    const float* kbase = qkv + (size_t)b * TT * 3 * DD + DD + h * HD;
    const float* vbase = kbase + DD;
    float m = -1e30f, l = 0.f, a0 = 0.f, a1 = 0.f;
    for (int jb = 0; jb <= t; jb += 32) {
        int j = jb + lane;
        float s = -1e30f;
        {
            const float4* kp = (const float4*)(kbase + (size_t)j * (3 * DD));
            float ss = 0.f;
            if (j <= t) {
#pragma unroll
                for (int d4 = 0; d4 < 16; d4++) {
                    float4 kv = kp[d4];
                    float qq = (d4 < 8) ? q0 : q1;
                    ss += kv.x * __shfl_sync(0xffffffffu, qq, (4 * d4 + 0) & 31);
                    ss += kv.y * __shfl_sync(0xffffffffu, qq, (4 * d4 + 1) & 31);
                    ss += kv.z * __shfl_sync(0xffffffffu, qq, (4 * d4 + 2) & 31);
                    ss += kv.w * __shfl_sync(0xffffffffu, qq, (4 * d4 + 3) & 31);
                }
                s = ss;
            } else {
                // keep shfl participation for inactive lanes
#pragma unroll
                for (int d4 = 0; d4 < 16; d4++) {
                    float qq = (d4 < 8) ? q0 : q1;
                    ss += __shfl_sync(0xffffffffu, qq, (4 * d4 + 0) & 31);
                    ss += __shfl_sync(0xffffffffu, qq, (4 * d4 + 1) & 31);
                    ss += __shfl_sync(0xffffffffu, qq, (4 * d4 + 2) & 31);
                    ss += __shfl_sync(0xffffffffu, qq, (4 * d4 + 3) & 31);
                }
            }
        }
        float bmx = warp_max(s);
        float mn = fmaxf(m, bmx);
        float corr = __expf(m - mn);
        float p = __expf(s - mn);          // masked lanes -> 0
        l = l * corr + warp_sum(p);
        a0 *= corr;
        a1 *= corr;
        int nkeys = min(t - jb + 1, 32);
        for (int j2 = 0; j2 < nkeys; j2++) {
            float pj = __shfl_sync(0xffffffffu, p, j2);
            const float* vp = vbase + (size_t)(jb + j2) * (3 * DD);
            a0 += pj * vp[lane];
            a1 += pj * vp[32 + lane];
        }
        m = mn;
    }
    float inv = 1.f / l;
    a0 *= inv;
    a1 *= inv;
    size_t oy = (size_t)(b * TT + t) * DD + h * HD;
    __nv_bfloat16 hh, ll;
    split2(a0, hh, ll); yhi[oy + lane] = hh;      ylo[oy + lane] = ll;
    split2(a1, hh, ll); yhi[oy + 32 + lane] = hh; ylo[oy + 32 + lane] = ll;
}

// ---- loss ----
template <bool DYN>
__global__ void loss_rows_kernel(const void* __restrict__ logits,
                                 const int* __restrict__ targets,
                                 float* __restrict__ rowloss) {
    __shared__ float sh[8];
    const int bf = DYN ? g_bf16 : 0;
    int row = blockIdx.x, tid = threadIdx.x;
    const size_t base = (size_t)row * VV;
    float mx = -1e30f;
    for (int c = tid; c < VV; c += 256)
        mx = fmaxf(mx, load_dyn(logits, base + c, bf));
    mx = block_max(mx, sh);
    float s = 0.f;
    for (int c = tid; c < VV; c += 256)
        s += __expf(load_dyn(logits, base + c, bf) - mx);
    s = block_sum(s, sh);
    if (tid == 0) {
        int tg = targets[row];
        if (tg < 0) tg = 0;
        if (tg >= VV) tg = VV - 1;
        float lt = load_dyn(logits, base + tg, bf);
        rowloss[row] = -(lt - mx - logf(s));
    }
}
__global__ void loss_final_kernel(const float* __restrict__ rowloss,
                                  void* __restrict__ out, long long elem_off) {
    __shared__ float sh[8];
    const int bf = g_bf16;
    float s = 0.f;
    for (int i = threadIdx.x; i < MM; i += 256) s += rowloss[i];
    s = block_sum(s, sh);
    if (threadIdx.x == 0) {
        float v = s * (1.f / (float)MM);
        if (bf) ((__nv_bfloat16*)out)[elem_off] = __float2bfloat16(v);
        else    ((float*)out)[elem_off] = v;
    }
}

static inline void cvt(const void* src, float* dst, long long n) {
    int grid = (int)((n + 255) / 256);
    if (grid > 4096) grid = 4096;
    cvt_kernel<<<grid, 256>>>(src, dst, (int)n);
}

extern "C" void kernel_launch(void* const* d_in, const int* in_sizes, int n_in,
                              void* d_out, int out_size) {
    const int *idx, *targets;
    const void *wte, *wpe, *ln1_s, *ln1_b, *attn_w, *attn_b, *proj_w, *proj_b;
    const void *ln2_s, *ln2_b, *fc_w, *fc_b, *proj2_w, *proj2_b, *lnf_s, *lnf_b;

    if (n_in >= 18 && in_sizes[0] != 2048) {
        attn_b  = d_in[0];  attn_w  = d_in[1];  fc_b    = d_in[2];  fc_w    = d_in[3];
        idx     = (const int*)d_in[4];
        ln1_b   = d_in[5];  ln1_s   = d_in[6];  ln2_b   = d_in[7];  ln2_s   = d_in[8];
        lnf_b   = d_in[9];  lnf_s   = d_in[10];
        proj2_b = d_in[11]; proj2_w = d_in[12]; proj_b  = d_in[13]; proj_w  = d_in[14];
        targets = (const int*)d_in[15];
        wpe     = d_in[16]; wte     = d_in[17];
    } else {
        idx     = (const int*)d_in[0];
        targets = (const int*)d_in[1];
        wte     = d_in[2];  wpe     = d_in[3];
        ln1_s   = d_in[4];  ln1_b   = d_in[5];
        attn_w  = d_in[6];  attn_b  = d_in[7];
        proj_w  = d_in[8];  proj_b  = d_in[9];
        ln2_s   = d_in[10]; ln2_b   = d_in[11];
        fc_w    = d_in[12]; fc_b    = d_in[13];
        proj2_w = d_in[14]; proj2_b = d_in[15];
        lnf_s   = d_in[16]; lnf_b   = d_in[17];
    }

    float *x, *qkv, *rowloss, *logits_scratch;
    cudaGetSymbolAddress((void**)&x, g_x);
    cudaGetSymbolAddress((void**)&qkv, g_qkv);
    cudaGetSymbolAddress((void**)&rowloss, g_rowloss);
    cudaGetSymbolAddress((void**)&logits_scratch, g_logits);

    __nv_bfloat16 *hhi, *hlo, *yhi, *ylo, *fchi, *fclo;
    cudaGetSymbolAddress((void**)&hhi, g_h_hi);
    cudaGetSymbolAddress((void**)&hlo, g_h_lo);
    cudaGetSymbolAddress((void**)&yhi, g_y_hi);
    cudaGetSymbolAddress((void**)&ylo, g_y_lo);
    cudaGetSymbolAddress((void**)&fchi, g_fc_hi);
    cudaGetSymbolAddress((void**)&fclo, g_fc_lo);

    float *wtef, *wpef, *ln1sf, *ln1bf, *attnbf, *projbf;
    float *ln2sf, *ln2bf, *fcbf, *p2bf, *lnfsf, *lnfbf;
    cudaGetSymbolAddress((void**)&wtef, cw_wte);
    cudaGetSymbolAddress((void**)&wpef, cw_wpe);
    cudaGetSymbolAddress((void**)&ln1sf, cw_ln1s);
    cudaGetSymbolAddress((void**)&ln1bf, cw_ln1b);
    cudaGetSymbolAddress((void**)&attnbf, cw_attnb);
    cudaGetSymbolAddress((void**)&projbf, cw_projb);
    cudaGetSymbolAddress((void**)&ln2sf, cw_ln2s);
    cudaGetSymbolAddress((void**)&ln2bf, cw_ln2b);
    cudaGetSymbolAddress((void**)&fcbf, cw_fcb);
    cudaGetSymbolAddress((void**)&p2bf, cw_p2b);
    cudaGetSymbolAddress((void**)&lnfsf, cw_lnfs);
    cudaGetSymbolAddress((void**)&lnfbf, cw_lnfb);

    __nv_bfloat16 *awh, *awl, *pwh, *pwl, *fwh, *fwl, *p2h, *p2l, *wth, *wtl;
    cudaGetSymbolAddress((void**)&awh, tw_attn_hi);
    cudaGetSymbolAddress((void**)&awl, tw_attn_lo);
    cudaGetSymbolAddress((void**)&pwh, tw_proj_hi);
    cudaGetSymbolAddress((void**)&pwl, tw_proj_lo);
    cudaGetSymbolAddress((void**)&fwh, tw_fc_hi);
    cudaGetSymbolAddress((void**)&fwl, tw_fc_lo);
    cudaGetSymbolAddress((void**)&p2h, tw_p2_hi);
    cudaGetSymbolAddress((void**)&p2l, tw_p2_lo);
    cudaGetSymbolAddress((void**)&wth, wte_hi);
    cudaGetSymbolAddress((void**)&wtl, wte_lo);

    // 1) dtype detection
    detect_kernel<<<1, 32>>>((const uint32_t*)wte);

    // 2) canonical params + split weights
    cvt(wte,    wtef,  (long long)VV * DD);
    cvt(wpe,    wpef,  TT * DD);
    cvt(ln1_s,  ln1sf, LL * DD);
    cvt(ln1_b,  ln1bf, LL * DD);
    cvt(attn_b, attnbf, LL * 3 * DD);
    cvt(proj_b, projbf, LL * DD);
    cvt(ln2_s,  ln2sf, LL * DD);
    cvt(ln2_b,  ln2bf, LL * DD);
    cvt(fc_b,   fcbf,  LL * 4 * DD);
    cvt(proj2_b, p2bf, LL * DD);
    cvt(lnf_s,  lnfsf, DD);
    cvt(lnf_b,  lnfbf, DD);

    wsplit_kernel<<<8192, 256>>>(wte, wth, wtl, (long long)VV * DD);
    tsplit_kernel<<<dim3(3 * DD / 32, DD / 32, LL), dim3(32, 8)>>>(attn_w,  awh, awl, DD, 3 * DD);
    tsplit_kernel<<<dim3(DD / 32, DD / 32, LL),     dim3(32, 8)>>>(proj_w,  pwh, pwl, DD, DD);
    tsplit_kernel<<<dim3(4 * DD / 32, DD / 32, LL), dim3(32, 8)>>>(fc_w,    fwh, fwl, DD, 4 * DD);
    tsplit_kernel<<<dim3(DD / 32, 4 * DD / 32, LL), dim3(32, 8)>>>(proj2_w, p2h, p2l, 4 * DD, DD);

    const long long NL = (long long)MM * VV;
    const bool logits_fit = ((long long)out_size >= NL);

    embed_kernel<<<MM, 256>>>(idx, wtef, wpef, x);

    for (int l = 0; l < LL; l++) {
        const size_t wo_a = (size_t)l * 3 * DD * DD;
        const size_t wo_p = (size_t)l * DD * DD;
        const size_t wo_f = (size_t)l * 4 * DD * DD;
        // attention block
        ln_kernel<<<MM, 256>>>(x, ln1sf + l * DD, ln1bf + l * DD, hhi, hlo);
        hgemm_kernel<4, 0, 0, false><<<dim3(3 * DD / 128, MM / 128), 256>>>(
            hhi, hlo, awh + wo_a, awl + wo_a, attnbf + l * 3 * DD, nullptr,
            qkv, nullptr, 3 * DD, DD);
        attn_kernel<<<dim3(TT / 8, HH, BB), 256>>>(qkv, yhi, ylo);
        hgemm_kernel<2, 2, 0, false><<<dim3(DD / 128, MM / 64), 256>>>(
            yhi, ylo, pwh + wo_p, pwl + wo_p, projbf + l * DD, x, x, nullptr, DD, DD);
        // MLP block
        ln_kernel<<<MM, 256>>>(x, ln2sf + l * DD, ln2bf + l * DD, hhi, hlo);
        hgemm_kernel<4, 1, 1, false><<<dim3(4 * DD / 128, MM / 128), 256>>>(
            hhi, hlo, fwh + wo_f, fwl + wo_f, fcbf + l * 4 * DD, nullptr,
            fchi, fclo, 4 * DD, DD);
        hgemm_kernel<2, 2, 0, false><<<dim3(DD / 128, MM / 64), 256>>>(
            fchi, fclo, p2h + wo_f, p2l + wo_f, p2bf + l * DD, x, x, nullptr, DD, 4 * DD);
    }

    // final LN + tied lm_head
    ln_kernel<<<MM, 256>>>(x, lnfsf, lnfbf, hhi, hlo);
    if (logits_fit) {
        hgemm_kernel<4, 3, 2, true><<<dim3((VV + 127) / 128, MM / 128), 256>>>(
            hhi, hlo, wth, wtl, nullptr, nullptr, d_out, nullptr, VV, DD);
        if ((long long)out_size > NL) {
            loss_rows_kernel<true><<<MM, 256>>>(d_out, targets, rowloss);
            loss_final_kernel<<<1, 256>>>(rowloss, d_out, NL);
        }
    } else {
        hgemm_kernel<4, 3, 0, true><<<dim3((VV + 127) / 128, MM / 128), 256>>>(
            hhi, hlo, wth, wtl, nullptr, nullptr, logits_scratch, nullptr, VV, DD);
        if (out_size >= 1) {
            loss_rows_kernel<false><<<MM, 256>>>(logits_scratch, targets, rowloss);
            loss_final_kernel<<<1, 256>>>(rowloss, d_out, 0);
        }
    }
}